// round 5
// baseline (speedup 1.0000x reference)
#include <cuda_runtime.h>
#include <math.h>
#include <stdint.h>

#define D_MODEL 1024
#define NUM_HEADS 16
#define DK 64
#define BATCH 4
#define SEQ 2048
#define MTOT (BATCH * SEQ)   // 8192

// Scratch (no allocation allowed)
__device__ float g_Q[MTOT * D_MODEL];
__device__ float g_K[MTOT * D_MODEL];
__device__ float g_V[MTOT * D_MODEL];
__device__ float g_O[MTOT * D_MODEL];
__device__ float g_Wc[4 * D_MODEL * D_MODEL];   // tf32-rounded weights

// ---------------------------------------------------------------------------
// Helpers
// ---------------------------------------------------------------------------
__device__ __forceinline__ uint32_t f2tf32(float x) {
    uint32_t r;
    asm("cvt.rn.tf32.f32 %0, %1;" : "=r"(r) : "f"(x));
    return r;
}
__device__ __forceinline__ float f2tf32f(float x) {
    return __uint_as_float(f2tf32(x));
}
__device__ __forceinline__ uint32_t u2tf32(uint32_t u) {
    return f2tf32(__uint_as_float(u));
}
__device__ __forceinline__ uint32_t fbits(float x) { return __float_as_uint(x); }

// D += A*B : m16n8k8 tf32.
__device__ __forceinline__ void mma8(float c[4], uint32_t a0, uint32_t a1,
                                     uint32_t a2, uint32_t a3,
                                     uint32_t b0, uint32_t b1) {
    asm volatile(
        "mma.sync.aligned.m16n8k8.row.col.f32.tf32.tf32.f32 "
        "{%0,%1,%2,%3}, {%4,%5,%6,%7}, {%8,%9}, {%0,%1,%2,%3};"
        : "+f"(c[0]), "+f"(c[1]), "+f"(c[2]), "+f"(c[3])
        : "r"(a0), "r"(a1), "r"(a2), "r"(a3), "r"(b0), "r"(b1));
}

__device__ __forceinline__ void ldsm4(uint32_t r[4], uint32_t saddr) {
    asm volatile(
        "ldmatrix.sync.aligned.m8n8.x4.shared.b16 {%0,%1,%2,%3}, [%4];"
        : "=r"(r[0]), "=r"(r[1]), "=r"(r[2]), "=r"(r[3]) : "r"(saddr));
}

__device__ __forceinline__ void cp_async16(void* smem, const void* gmem) {
    uint32_t s = (uint32_t)__cvta_generic_to_shared(smem);
    asm volatile("cp.async.cg.shared.global [%0], [%1], 16;" :: "r"(s), "l"(gmem));
}
__device__ __forceinline__ void cp_commit() {
    asm volatile("cp.async.commit_group;");
}
template <int N>
__device__ __forceinline__ void cp_wait() {
    asm volatile("cp.async.wait_group %0;" :: "n"(N));
}

// ---------------------------------------------------------------------------
// Weight pre-round: dst = tf32_rn(src), 1024x1024
// ---------------------------------------------------------------------------
__global__ __launch_bounds__(256) void cvt_w(const float* __restrict__ src,
                                             float* __restrict__ dst)
{
    int i = (blockIdx.x * 256 + threadIdx.x) * 4;
    float4 v = *(const float4*)(src + i);
    *(float4*)(dst + i) = make_float4(f2tf32f(v.x), f2tf32f(v.y),
                                      f2tf32f(v.z), f2tf32f(v.w));
}

// ---------------------------------------------------------------------------
// GEMM: C[8192,1024] = A @ Wc^T + bias. Wc pre-rounded tf32 (raw fragments);
// A converted in-register after ldmatrix. cp.async 4-stage pipeline.
// CTA 128x128, 8 warps (4x2), warp tile 32x64, BK=16.
// ---------------------------------------------------------------------------
#define GPITCH 20
#define GSTG   4
#define GSTAGE (128 * GPITCH)
#define GEMM_SMEM (GSTG * 2 * GSTAGE * 4) // 81920 B

__global__ __launch_bounds__(256, 2) void gemm_mma(
    const float* __restrict__ A, const float* __restrict__ W,
    const float* __restrict__ bias, float* __restrict__ C, int round_out)
{
    extern __shared__ __align__(16) float sg[];
    float* As = sg;
    float* Ws = sg + GSTG * GSTAGE;

    const int tid = threadIdx.x;
    const int lane = tid & 31;
    const int g = lane >> 2, tig = lane & 3;
    const int wid = tid >> 5;
    const int wm = wid & 3;
    const int wn = wid >> 2;
    const int row0 = blockIdx.y * 128;
    const int col0 = blockIdx.x * 128;

    const float* Ag = A + (size_t)row0 * D_MODEL;
    const float* Wg = W + (size_t)col0 * D_MODEL;

    const uint32_t sA = (uint32_t)__cvta_generic_to_shared(As);
    const uint32_t sW = (uint32_t)__cvta_generic_to_shared(Ws);

    auto load_stage = [&](int ch, int st) {
        const int kof = ch * 16;
#pragma unroll
        for (int j = 0; j < 2; j++) {
            int slot = tid + j * 256;
            int r = slot >> 2, c = (slot & 3) * 4;
            cp_async16(&As[st * GSTAGE + r * GPITCH + c],
                       Ag + (size_t)r * D_MODEL + kof + c);
            cp_async16(&Ws[st * GSTAGE + r * GPITCH + c],
                       Wg + (size_t)r * D_MODEL + kof + c);
        }
        cp_commit();
    };
    load_stage(0, 0);
    load_stage(1, 1);
    load_stage(2, 2);

    float acc[2][8][4];
#pragma unroll
    for (int mt = 0; mt < 2; mt++)
#pragma unroll
        for (int nt = 0; nt < 8; nt++)
#pragma unroll
            for (int i = 0; i < 4; i++) acc[mt][nt][i] = 0.0f;

    const int a_row = lane & 15;
    const int a_byt = (lane >> 4) << 4;
    const int b_row = ((lane >> 4) << 3) + (lane & 7);
    const int b_byt = ((lane >> 3) & 1) << 4;

    for (int ch = 0; ch < 64; ch++) {
        const int p = ch & 3;
        if (ch < 62) cp_wait<2>();
        else if (ch == 62) cp_wait<1>();
        else cp_wait<0>();
        __syncthreads();
        if (ch + 3 < 64) load_stage(ch + 3, (ch + 3) & 3);

        const uint32_t aBase = sA + p * (GSTAGE * 4);
        const uint32_t wBase = sW + p * (GSTAGE * 4);
#pragma unroll
        for (int kk = 0; kk < 2; kk++) {
            uint32_t ua[2][4];
#pragma unroll
            for (int mt = 0; mt < 2; mt++) {
                ldsm4(ua[mt], aBase + (wm * 32 + mt * 16 + a_row) * (GPITCH * 4)
                              + kk * 32 + a_byt);
#pragma unroll
                for (int i = 0; i < 4; i++) ua[mt][i] = u2tf32(ua[mt][i]);
            }
#pragma unroll
            for (int nt2 = 0; nt2 < 4; nt2++) {
                uint32_t ub[4];
                ldsm4(ub, wBase + (wn * 64 + nt2 * 16 + b_row) * (GPITCH * 4)
                          + kk * 32 + b_byt);
                mma8(acc[0][nt2 * 2],     ua[0][0], ua[0][1], ua[0][2], ua[0][3], ub[0], ub[1]);
                mma8(acc[1][nt2 * 2],     ua[1][0], ua[1][1], ua[1][2], ua[1][3], ub[0], ub[1]);
                mma8(acc[0][nt2 * 2 + 1], ua[0][0], ua[0][1], ua[0][2], ua[0][3], ub[2], ub[3]);
                mma8(acc[1][nt2 * 2 + 1], ua[1][0], ua[1][1], ua[1][2], ua[1][3], ub[2], ub[3]);
            }
        }
    }

#pragma unroll
    for (int mt = 0; mt < 2; mt++) {
        const int ra = row0 + wm * 32 + mt * 16 + g;
#pragma unroll
        for (int nt = 0; nt < 8; nt++) {
            const int col = col0 + wn * 64 + nt * 8 + 2 * tig;
            const float bz0 = bias[col], bz1 = bias[col + 1];
            float v0 = acc[mt][nt][0] + bz0, v1 = acc[mt][nt][1] + bz1;
            float v2 = acc[mt][nt][2] + bz0, v3 = acc[mt][nt][3] + bz1;
            if (round_out) {
                v0 = f2tf32f(v0); v1 = f2tf32f(v1);
                v2 = f2tf32f(v2); v3 = f2tf32f(v3);
            }
            *(float2*)(C + (size_t)ra * D_MODEL + col) = make_float2(v0, v1);
            *(float2*)(C + (size_t)(ra + 8) * D_MODEL + col) = make_float2(v2, v3);
        }
    }
}

// ---------------------------------------------------------------------------
// Flash attention v3: CTA per (b,h,128 q-rows), Bc=64, 8 warps x 16 rows.
// V transposed in smem each block -> PV B-fragments via ldmatrix (no scalar LDS).
// smem: K[2][64*68] | V[2][64*72] | Vt[64*68]
// ---------------------------------------------------------------------------
#define KP 68
#define VP 72
#define TP 68
#define ATTN_SMEM ((2 * 64 * KP + 2 * 64 * VP + 64 * TP) * 4)  // 89088 B

__global__ __launch_bounds__(256, 1) void attn_mma(
    const float* __restrict__ Q, const float* __restrict__ K,
    const float* __restrict__ V, float* __restrict__ O)
{
    extern __shared__ __align__(16) float smf[];
    float* Ks = smf;                    // 2 * 64*KP
    float* Vs = smf + 2 * 64 * KP;      // 2 * 64*VP
    float* Vt = Vs + 2 * 64 * VP;       // 64*TP  (V^T: [d][k])
    float* Qst = smf;                   // overlay on K region: 128*KP

    const int tid = threadIdx.x;
    const int lane = tid & 31;
    const int g = lane >> 2, tig = lane & 3;
    const int wid = tid >> 5;
    const int qb = wid * 16;

    const int b = blockIdx.y >> 4;
    const int h = blockIdx.y & 15;
    const int q0 = blockIdx.x * 128;
    const size_t base = (size_t)b * SEQ * D_MODEL + (size_t)h * DK;

    // Stage Q (x 1/8, pow2 -> tf32-exact) and lift A-fragments.
    for (int i = tid; i < 128 * 16; i += 256) {
        int r = i >> 4, c4 = (i & 15) * 4;
        float4 qv = *(const float4*)(Q + base + (size_t)(q0 + r) * D_MODEL + c4);
        qv.x *= 0.125f; qv.y *= 0.125f; qv.z *= 0.125f; qv.w *= 0.125f;
        *(float4*)&Qst[r * KP + c4] = qv;
    }
    __syncthreads();

    const uint32_t sQ = (uint32_t)__cvta_generic_to_shared(Qst);
    const uint32_t sK = (uint32_t)__cvta_generic_to_shared(Ks);
    const uint32_t sVt = (uint32_t)__cvta_generic_to_shared(Vt);
    const int a_row = lane & 15;
    const int a_byt = (lane >> 4) << 4;
    const int b_row = ((lane >> 4) << 3) + (lane & 7);
    const int b_byt = ((lane >> 3) & 1) << 4;

    uint32_t qa[8][4];
#pragma unroll
    for (int kk = 0; kk < 8; kk++)
        ldsm4(qa[kk], sQ + (qb + a_row) * (KP * 4) + kk * 32 + a_byt);
    __syncthreads();

    auto load_blk = [&](int kb, int p) {
#pragma unroll
        for (int j = 0; j < 4; j++) {
            int slot = tid + j * 256;
            int r = slot >> 4, c4 = (slot & 15) * 4;
            const float* kg = K + base + (size_t)(kb * 64 + r) * D_MODEL + c4;
            const float* vg = V + base + (size_t)(kb * 64 + r) * D_MODEL + c4;
            cp_async16(&Ks[p * 64 * KP + r * KP + c4], kg);
            cp_async16(&Vs[p * 64 * VP + r * VP + c4], vg);
        }
        cp_commit();
    };
    load_blk(0, 0);
    load_blk(1, 1);

    float m0 = -INFINITY, m1 = -INFINITY, l0 = 0.0f, l1 = 0.0f;
    float oacc[8][4];
#pragma unroll
    for (int nt = 0; nt < 8; nt++)
#pragma unroll
        for (int i = 0; i < 4; i++) oacc[nt][i] = 0.0f;

    const int NB = SEQ / 64;  // 32
    for (int kb = 0; kb < NB; kb++) {
        const int p = kb & 1;
        if (kb < NB - 2) cp_wait<1>(); else cp_wait<0>();
        __syncthreads();

        // S = Q @ K^T
        float s[8][4];
#pragma unroll
        for (int nt = 0; nt < 8; nt++)
#pragma unroll
            for (int i = 0; i < 4; i++) s[nt][i] = 0.0f;

        const uint32_t kBase = sK + p * (64 * KP * 4);
#pragma unroll
        for (int kk = 0; kk < 8; kk++) {
#pragma unroll
            for (int nt2 = 0; nt2 < 4; nt2++) {
                uint32_t ub[4];
                ldsm4(ub, kBase + (nt2 * 16 + b_row) * (KP * 4) + kk * 32 + b_byt);
                mma8(s[nt2 * 2],     qa[kk][0], qa[kk][1], qa[kk][2], qa[kk][3], ub[0], ub[1]);
                mma8(s[nt2 * 2 + 1], qa[kk][0], qa[kk][1], qa[kk][2], qa[kk][3], ub[2], ub[3]);
            }
        }

        // Transpose V block -> Vt[d][k] (conflict-free both sides)
        {
            const float* Vp = Vs + p * 64 * VP;
#pragma unroll
            for (int j = 0; j < 4; j++) {
                int linear = tid + j * 256;
                int c = linear & 63;            // d column of V
                int r0 = (linear >> 6) * 4;     // k row group
                float x0 = Vp[(r0 + 0) * VP + c];
                float x1 = Vp[(r0 + 1) * VP + c];
                float x2 = Vp[(r0 + 2) * VP + c];
                float x3 = Vp[(r0 + 3) * VP + c];
                *(float4*)&Vt[c * TP + r0] = make_float4(x0, x1, x2, x3);
            }
        }
        __syncthreads();           // Vt ready; Ks[p]/Vs[p] fully consumed
        if (kb + 2 < NB) load_blk(kb + 2, p);   // overlap with softmax+PV

        // Online softmax (rows r0=qb+g, r1=qb+g+8)
        float rmax0 = -INFINITY, rmax1 = -INFINITY;
#pragma unroll
        for (int nt = 0; nt < 8; nt++) {
            rmax0 = fmaxf(rmax0, fmaxf(s[nt][0], s[nt][1]));
            rmax1 = fmaxf(rmax1, fmaxf(s[nt][2], s[nt][3]));
        }
        rmax0 = fmaxf(rmax0, __shfl_xor_sync(0xffffffffu, rmax0, 1));
        rmax0 = fmaxf(rmax0, __shfl_xor_sync(0xffffffffu, rmax0, 2));
        rmax1 = fmaxf(rmax1, __shfl_xor_sync(0xffffffffu, rmax1, 1));
        rmax1 = fmaxf(rmax1, __shfl_xor_sync(0xffffffffu, rmax1, 2));

        const float mn0 = fmaxf(m0, rmax0);
        const float mn1 = fmaxf(m1, rmax1);
        const float alpha0 = __expf(m0 - mn0);
        const float alpha1 = __expf(m1 - mn1);

        float rs0 = 0.0f, rs1 = 0.0f;
#pragma unroll
        for (int nt = 0; nt < 8; nt++) {
            s[nt][0] = __expf(s[nt][0] - mn0);
            s[nt][1] = __expf(s[nt][1] - mn0);
            s[nt][2] = __expf(s[nt][2] - mn1);
            s[nt][3] = __expf(s[nt][3] - mn1);
            rs0 += s[nt][0] + s[nt][1];
            rs1 += s[nt][2] + s[nt][3];
        }
        rs0 += __shfl_xor_sync(0xffffffffu, rs0, 1);
        rs0 += __shfl_xor_sync(0xffffffffu, rs0, 2);
        rs1 += __shfl_xor_sync(0xffffffffu, rs1, 1);
        rs1 += __shfl_xor_sync(0xffffffffu, rs1, 2);

        l0 = l0 * alpha0 + rs0;
        l1 = l1 * alpha1 + rs1;
        m0 = mn0; m1 = mn1;
#pragma unroll
        for (int nt = 0; nt < 8; nt++) {
            oacc[nt][0] *= alpha0; oacc[nt][1] *= alpha0;
            oacc[nt][2] *= alpha1; oacc[nt][3] *= alpha1;
        }

        // PV: A-frags via intra-quad shuffles of S; B-frags via ldmatrix on Vt.
        const int src0 = (lane & ~3) | (tig >> 1);
        const int src1 = src0 + 2;
        const bool odd = (tig & 1);
#pragma unroll
        for (int kk = 0; kk < 8; kk++) {
            float t00 = __shfl_sync(0xffffffffu, s[kk][0], src0);
            float t01 = __shfl_sync(0xffffffffu, s[kk][1], src0);
            float t02 = __shfl_sync(0xffffffffu, s[kk][2], src0);
            float t03 = __shfl_sync(0xffffffffu, s[kk][3], src0);
            float t10 = __shfl_sync(0xffffffffu, s[kk][0], src1);
            float t11 = __shfl_sync(0xffffffffu, s[kk][1], src1);
            float t12 = __shfl_sync(0xffffffffu, s[kk][2], src1);
            float t13 = __shfl_sync(0xffffffffu, s[kk][3], src1);
            uint32_t a0 = f2tf32(odd ? t01 : t00);
            uint32_t a1 = f2tf32(odd ? t03 : t02);
            uint32_t a2 = f2tf32(odd ? t11 : t10);
            uint32_t a3 = f2tf32(odd ? t13 : t12);
#pragma unroll
            for (int nt2 = 0; nt2 < 4; nt2++) {
                uint32_t ub[4];
                ldsm4(ub, sVt + (nt2 * 16 + b_row) * (TP * 4) + kk * 32 + b_byt);
                mma8(oacc[nt2 * 2],     a0, a1, a2, a3, ub[0], ub[1]);
                mma8(oacc[nt2 * 2 + 1], a0, a1, a2, a3, ub[2], ub[3]);
            }
        }
        // next iteration's top __syncthreads protects Vt from early overwrite
    }

    const float inv0 = 1.0f / l0;
    const float inv1 = 1.0f / l1;
#pragma unroll
    for (int nt = 0; nt < 8; nt++) {
        const int col = nt * 8 + 2 * tig;
        const size_t ro0 = base + (size_t)(q0 + qb + g) * D_MODEL + col;
        const size_t ro1 = base + (size_t)(q0 + qb + g + 8) * D_MODEL + col;
        *(float2*)(O + ro0) = make_float2(oacc[nt][0] * inv0, oacc[nt][1] * inv0);
        *(float2*)(O + ro1) = make_float2(oacc[nt][2] * inv1, oacc[nt][3] * inv1);
    }
}

// ---------------------------------------------------------------------------
// Launch
// ---------------------------------------------------------------------------
extern "C" void kernel_launch(void* const* d_in, const int* in_sizes, int n_in,
                              void* d_out, int out_size)
{
    const float* q  = (const float*)d_in[0];
    const float* k  = (const float*)d_in[1];
    const float* v  = (const float*)d_in[2];
    const float* Wq = (const float*)d_in[3];
    const float* bq = (const float*)d_in[4];
    const float* Wk = (const float*)d_in[5];
    const float* bk = (const float*)d_in[6];
    const float* Wv = (const float*)d_in[7];
    const float* bv = (const float*)d_in[8];
    const float* Wo = (const float*)d_in[9];
    const float* bo = (const float*)d_in[10];
    float* out = (float*)d_out;

    float *pQ, *pK, *pV, *pO, *pWc;
    cudaGetSymbolAddress((void**)&pQ, g_Q);
    cudaGetSymbolAddress((void**)&pK, g_K);
    cudaGetSymbolAddress((void**)&pV, g_V);
    cudaGetSymbolAddress((void**)&pO, g_O);
    cudaGetSymbolAddress((void**)&pWc, g_Wc);

    cudaFuncSetAttribute(gemm_mma, cudaFuncAttributeMaxDynamicSharedMemorySize,
                         GEMM_SMEM);
    cudaFuncSetAttribute(attn_mma, cudaFuncAttributeMaxDynamicSharedMemorySize,
                         ATTN_SMEM);

    const int WN = D_MODEL * D_MODEL;
    cvt_w<<<WN / 1024, 256>>>(Wq, pWc + 0 * WN);
    cvt_w<<<WN / 1024, 256>>>(Wk, pWc + 1 * WN);
    cvt_w<<<WN / 1024, 256>>>(Wv, pWc + 2 * WN);
    cvt_w<<<WN / 1024, 256>>>(Wo, pWc + 3 * WN);

    dim3 gGemm(D_MODEL / 128, MTOT / 128);  // (8, 64)
    gemm_mma<<<gGemm, 256, GEMM_SMEM>>>(q, pWc + 0 * WN, bq, pQ, 1);
    gemm_mma<<<gGemm, 256, GEMM_SMEM>>>(k, pWc + 1 * WN, bk, pK, 1);
    gemm_mma<<<gGemm, 256, GEMM_SMEM>>>(v, pWc + 2 * WN, bv, pV, 1);

    dim3 gAttn(SEQ / 128, BATCH * NUM_HEADS);  // (16, 64)
    attn_mma<<<gAttn, 256, ATTN_SMEM>>>(pQ, pK, pV, pO);

    gemm_mma<<<gGemm, 256, GEMM_SMEM>>>(pO, pWc + 3 * WN, bo, out, 0);
}

// round 6
// speedup vs baseline: 2.0027x; 2.0027x over previous
#include <cuda_runtime.h>
#include <cuda_fp16.h>
#include <math.h>
#include <stdint.h>

#define D_MODEL 1024
#define NUM_HEADS 16
#define DK 64
#define BATCH 4
#define SEQ 2048
#define MTOT (BATCH * SEQ)   // 8192

// Scratch (no allocation allowed) — fp16 intermediates
__device__ __half g_qh[MTOT * D_MODEL];
__device__ __half g_kh[MTOT * D_MODEL];
__device__ __half g_vh[MTOT * D_MODEL];
__device__ __half g_Qh[MTOT * D_MODEL];
__device__ __half g_Kh[MTOT * D_MODEL];
__device__ __half g_Vh[MTOT * D_MODEL];
__device__ __half g_Oh[MTOT * D_MODEL];
__device__ __half g_Wh[4 * D_MODEL * D_MODEL];

// ---------------------------------------------------------------------------
// Helpers
// ---------------------------------------------------------------------------
__device__ __forceinline__ uint32_t packh2(float a, float b) {
    __half2 h = __floats2half2_rn(a, b);
    return *reinterpret_cast<uint32_t*>(&h);
}

// D += A*B : m16n8k16 fp16 inputs, fp32 accumulate.
__device__ __forceinline__ void mma16(float c[4], uint32_t a0, uint32_t a1,
                                      uint32_t a2, uint32_t a3,
                                      uint32_t b0, uint32_t b1) {
    asm volatile(
        "mma.sync.aligned.m16n8k16.row.col.f32.f16.f16.f32 "
        "{%0,%1,%2,%3}, {%4,%5,%6,%7}, {%8,%9}, {%0,%1,%2,%3};"
        : "+f"(c[0]), "+f"(c[1]), "+f"(c[2]), "+f"(c[3])
        : "r"(a0), "r"(a1), "r"(a2), "r"(a3), "r"(b0), "r"(b1));
}

__device__ __forceinline__ void ldsm4(uint32_t r[4], uint32_t saddr) {
    asm volatile(
        "ldmatrix.sync.aligned.m8n8.x4.shared.b16 {%0,%1,%2,%3}, [%4];"
        : "=r"(r[0]), "=r"(r[1]), "=r"(r[2]), "=r"(r[3]) : "r"(saddr));
}
__device__ __forceinline__ void ldsm4t(uint32_t r[4], uint32_t saddr) {
    asm volatile(
        "ldmatrix.sync.aligned.m8n8.x4.trans.shared.b16 {%0,%1,%2,%3}, [%4];"
        : "=r"(r[0]), "=r"(r[1]), "=r"(r[2]), "=r"(r[3]) : "r"(saddr));
}

__device__ __forceinline__ void cp_async16(void* smem, const void* gmem) {
    uint32_t s = (uint32_t)__cvta_generic_to_shared(smem);
    asm volatile("cp.async.cg.shared.global [%0], [%1], 16;" :: "r"(s), "l"(gmem));
}
__device__ __forceinline__ void cp_commit() {
    asm volatile("cp.async.commit_group;");
}
template <int N>
__device__ __forceinline__ void cp_wait() {
    asm volatile("cp.async.wait_group %0;" :: "n"(N));
}

// ---------------------------------------------------------------------------
// fp32 -> fp16 RN conversion pass (8 elems/thread)
// ---------------------------------------------------------------------------
__global__ __launch_bounds__(256) void cvt_f2h(const float* __restrict__ src,
                                               __half* __restrict__ dst)
{
    int i = (blockIdx.x * 256 + threadIdx.x) * 8;
    float4 v0 = *(const float4*)(src + i);
    float4 v1 = *(const float4*)(src + i + 4);
    __half2 h[4];
    h[0] = __floats2half2_rn(v0.x, v0.y);
    h[1] = __floats2half2_rn(v0.z, v0.w);
    h[2] = __floats2half2_rn(v1.x, v1.y);
    h[3] = __floats2half2_rn(v1.z, v1.w);
    *(uint4*)(dst + i) = *(uint4*)h;
}

// ---------------------------------------------------------------------------
// fp16 GEMM: C[8192,1024] = A @ W^T + bias. A,W fp16; accumulate fp32.
// CTA 128x128, 8 warps (4x2), warp 32x64, BK=32 halves, cp.async 4-stage.
// OUT_HALF=1 -> fp16 output (feeds attention); else fp32.
// ---------------------------------------------------------------------------
#define HP 40                              // smem pitch (halves), 80B rows
#define HSTG 4
#define HSTAGE (128 * HP)                  // halves per matrix per stage
#define GEMM_SMEM (HSTG * 2 * HSTAGE * 2)  // 81920 B

template <int OUT_HALF>
__global__ __launch_bounds__(256, 2) void gemm_h(
    const __half* __restrict__ A, const __half* __restrict__ W,
    const float* __restrict__ bias, void* __restrict__ Cout)
{
    extern __shared__ __align__(16) __half sgh[];
    __half* As = sgh;
    __half* Ws = sgh + HSTG * HSTAGE;

    const int tid = threadIdx.x;
    const int lane = tid & 31;
    const int g = lane >> 2, tig = lane & 3;
    const int wid = tid >> 5;
    const int wm = wid & 3;
    const int wn = wid >> 2;
    const int row0 = blockIdx.y * 128;
    const int col0 = blockIdx.x * 128;

    const __half* Ag = A + (size_t)row0 * D_MODEL;
    const __half* Wg = W + (size_t)col0 * D_MODEL;

    const uint32_t sA = (uint32_t)__cvta_generic_to_shared(As);
    const uint32_t sW = (uint32_t)__cvta_generic_to_shared(Ws);

    // stage: 128 rows x 32 halves (64B) per matrix = 512 x 16B chunks each
    auto load_stage = [&](int ch, int st) {
        const int kof = ch * 32;
#pragma unroll
        for (int j = 0; j < 2; j++) {
            int slot = tid + j * 256;
            int r = slot >> 2, c = (slot & 3) * 8;
            cp_async16(&As[st * HSTAGE + r * HP + c],
                       Ag + (size_t)r * D_MODEL + kof + c);
            cp_async16(&Ws[st * HSTAGE + r * HP + c],
                       Wg + (size_t)r * D_MODEL + kof + c);
        }
        cp_commit();
    };
    load_stage(0, 0);
    load_stage(1, 1);
    load_stage(2, 2);

    float acc[2][8][4];
#pragma unroll
    for (int mt = 0; mt < 2; mt++)
#pragma unroll
        for (int nt = 0; nt < 8; nt++)
#pragma unroll
            for (int i = 0; i < 4; i++) acc[mt][nt][i] = 0.0f;

    const int a_row = lane & 15;
    const int a_byt = (lane >> 4) << 4;
    const int b_row = (lane & 7) + ((lane >> 4) << 3);
    const int b_byt = ((lane >> 3) & 1) << 4;

    const int NCH = D_MODEL / 32;  // 32
    for (int ch = 0; ch < NCH; ch++) {
        const int p = ch & 3;
        if (ch < NCH - 2) cp_wait<2>();
        else if (ch == NCH - 2) cp_wait<1>();
        else cp_wait<0>();
        __syncthreads();
        if (ch + 3 < NCH) load_stage(ch + 3, (ch + 3) & 3);

        const uint32_t aBase = sA + p * (HSTAGE * 2);
        const uint32_t wBase = sW + p * (HSTAGE * 2);
#pragma unroll
        for (int kk = 0; kk < 2; kk++) {
            uint32_t ua[2][4];
#pragma unroll
            for (int mt = 0; mt < 2; mt++)
                ldsm4(ua[mt], aBase + (wm * 32 + mt * 16 + a_row) * (HP * 2)
                              + kk * 32 + a_byt);
#pragma unroll
            for (int nt2 = 0; nt2 < 4; nt2++) {
                uint32_t ub[4];
                ldsm4(ub, wBase + (wn * 64 + nt2 * 16 + b_row) * (HP * 2)
                          + kk * 32 + b_byt);
                mma16(acc[0][nt2 * 2],     ua[0][0], ua[0][1], ua[0][2], ua[0][3], ub[0], ub[1]);
                mma16(acc[1][nt2 * 2],     ua[1][0], ua[1][1], ua[1][2], ua[1][3], ub[0], ub[1]);
                mma16(acc[0][nt2 * 2 + 1], ua[0][0], ua[0][1], ua[0][2], ua[0][3], ub[2], ub[3]);
                mma16(acc[1][nt2 * 2 + 1], ua[1][0], ua[1][1], ua[1][2], ua[1][3], ub[2], ub[3]);
            }
        }
    }

#pragma unroll
    for (int mt = 0; mt < 2; mt++) {
        const int ra = row0 + wm * 32 + mt * 16 + g;
#pragma unroll
        for (int nt = 0; nt < 8; nt++) {
            const int col = col0 + wn * 64 + nt * 8 + 2 * tig;
            const float bz0 = bias[col], bz1 = bias[col + 1];
            float v0 = acc[mt][nt][0] + bz0, v1 = acc[mt][nt][1] + bz1;
            float v2 = acc[mt][nt][2] + bz0, v3 = acc[mt][nt][3] + bz1;
            if (OUT_HALF) {
                __half* C = (__half*)Cout;
                *(__half2*)(C + (size_t)ra * D_MODEL + col) = __floats2half2_rn(v0, v1);
                *(__half2*)(C + (size_t)(ra + 8) * D_MODEL + col) = __floats2half2_rn(v2, v3);
            } else {
                float* C = (float*)Cout;
                *(float2*)(C + (size_t)ra * D_MODEL + col) = make_float2(v0, v1);
                *(float2*)(C + (size_t)(ra + 8) * D_MODEL + col) = make_float2(v2, v3);
            }
        }
    }
}

// ---------------------------------------------------------------------------
// fp16 flash attention: CTA per (b,h,128 q-rows), Bc=64, 8 warps x 16 rows.
// m16n8k16: P A-frags from S C-frags by register packing (no shuffles);
// V B-frags via ldmatrix.x4.trans (no smem transpose).
// smem: K[2][64*AKP] | V[2][64*AKP], Q staged over K region. 36864 B.
// ---------------------------------------------------------------------------
#define AKP 72
#define ATTN_SMEM (4 * 64 * AKP * 2)

__global__ __launch_bounds__(256, 2) void attn_h(
    const __half* __restrict__ Q, const __half* __restrict__ K,
    const __half* __restrict__ V, __half* __restrict__ O)
{
    extern __shared__ __align__(16) __half smh[];
    __half* Ks = smh;                   // 2 * 64*AKP
    __half* Vs = smh + 2 * 64 * AKP;    // 2 * 64*AKP
    __half* Qst = smh;                  // overlay (128*AKP == 2*64*AKP)

    const int tid = threadIdx.x;
    const int lane = tid & 31;
    const int g = lane >> 2, tig = lane & 3;
    const int wid = tid >> 5;
    const int qb = wid * 16;

    const int b = blockIdx.y >> 4;
    const int h = blockIdx.y & 15;
    const int q0 = blockIdx.x * 128;
    const size_t base = (size_t)b * SEQ * D_MODEL + (size_t)h * DK;

    // Stage Q (x 0.125, pow2-exact in fp16), lift A-fragments, release smem.
    {
        const __half2 sc = __half2half2(__float2half(0.125f));
        for (int i = tid; i < 128 * 8; i += 256) {
            int r = i >> 3, c8 = (i & 7) * 8;
            uint4 raw = *(const uint4*)(Q + base + (size_t)(q0 + r) * D_MODEL + c8);
            __half2* hp = (__half2*)&raw;
            hp[0] = __hmul2(hp[0], sc); hp[1] = __hmul2(hp[1], sc);
            hp[2] = __hmul2(hp[2], sc); hp[3] = __hmul2(hp[3], sc);
            *(uint4*)&Qst[r * AKP + c8] = raw;
        }
    }
    __syncthreads();

    const uint32_t sQ = (uint32_t)__cvta_generic_to_shared(Qst);
    const uint32_t sK = (uint32_t)__cvta_generic_to_shared(Ks);
    const uint32_t sV = (uint32_t)__cvta_generic_to_shared(Vs);
    const int a_row = lane & 15;
    const int a_byt = (lane >> 4) << 4;
    const int b_row = (lane & 7) + ((lane >> 4) << 3);
    const int b_byt = ((lane >> 3) & 1) << 4;
    const int v_row = (lane & 7) + (((lane >> 3) & 1) << 3);
    const int v_byt = (lane >> 4) << 4;

    uint32_t qa[4][4];
#pragma unroll
    for (int kk = 0; kk < 4; kk++)
        ldsm4(qa[kk], sQ + (qb + a_row) * (AKP * 2) + kk * 32 + a_byt);
    __syncthreads();

    // K/V block loader: 64 rows x 64 halves (128B = 8 x 16B) each
    auto load_blk = [&](int kb, int p) {
#pragma unroll
        for (int j = 0; j < 2; j++) {
            int slot = tid + j * 256;
            int r = slot >> 3, c8 = (slot & 7) * 8;
            const __half* kg = K + base + (size_t)(kb * 64 + r) * D_MODEL + c8;
            const __half* vg = V + base + (size_t)(kb * 64 + r) * D_MODEL + c8;
            cp_async16(&Ks[p * 64 * AKP + r * AKP + c8], kg);
            cp_async16(&Vs[p * 64 * AKP + r * AKP + c8], vg);
        }
        cp_commit();
    };
    load_blk(0, 0);
    load_blk(1, 1);

    float m0 = -INFINITY, m1 = -INFINITY, l0 = 0.0f, l1 = 0.0f;
    float oacc[8][4];
#pragma unroll
    for (int nt = 0; nt < 8; nt++)
#pragma unroll
        for (int i = 0; i < 4; i++) oacc[nt][i] = 0.0f;

    const int NB = SEQ / 64;  // 32
    for (int kb = 0; kb < NB; kb++) {
        const int p = kb & 1;
        if (kb < NB - 2) cp_wait<1>(); else cp_wait<0>();
        __syncthreads();

        // S = Q @ K^T
        float s[8][4];
#pragma unroll
        for (int nt = 0; nt < 8; nt++)
#pragma unroll
            for (int i = 0; i < 4; i++) s[nt][i] = 0.0f;

        const uint32_t kBase = sK + p * (64 * AKP * 2);
#pragma unroll
        for (int kk = 0; kk < 4; kk++) {
#pragma unroll
            for (int nt2 = 0; nt2 < 4; nt2++) {
                uint32_t ub[4];
                ldsm4(ub, kBase + (nt2 * 16 + b_row) * (AKP * 2) + kk * 32 + b_byt);
                mma16(s[nt2 * 2],     qa[kk][0], qa[kk][1], qa[kk][2], qa[kk][3], ub[0], ub[1]);
                mma16(s[nt2 * 2 + 1], qa[kk][0], qa[kk][1], qa[kk][2], qa[kk][3], ub[2], ub[3]);
            }
        }

        // Online softmax (rows r0=qb+g, r1=qb+g+8)
        float rmax0 = -INFINITY, rmax1 = -INFINITY;
#pragma unroll
        for (int nt = 0; nt < 8; nt++) {
            rmax0 = fmaxf(rmax0, fmaxf(s[nt][0], s[nt][1]));
            rmax1 = fmaxf(rmax1, fmaxf(s[nt][2], s[nt][3]));
        }
        rmax0 = fmaxf(rmax0, __shfl_xor_sync(0xffffffffu, rmax0, 1));
        rmax0 = fmaxf(rmax0, __shfl_xor_sync(0xffffffffu, rmax0, 2));
        rmax1 = fmaxf(rmax1, __shfl_xor_sync(0xffffffffu, rmax1, 1));
        rmax1 = fmaxf(rmax1, __shfl_xor_sync(0xffffffffu, rmax1, 2));

        const float mn0 = fmaxf(m0, rmax0);
        const float mn1 = fmaxf(m1, rmax1);
        const float alpha0 = __expf(m0 - mn0);
        const float alpha1 = __expf(m1 - mn1);

        float rs0 = 0.0f, rs1 = 0.0f;
#pragma unroll
        for (int nt = 0; nt < 8; nt++) {
            s[nt][0] = __expf(s[nt][0] - mn0);
            s[nt][1] = __expf(s[nt][1] - mn0);
            s[nt][2] = __expf(s[nt][2] - mn1);
            s[nt][3] = __expf(s[nt][3] - mn1);
            rs0 += s[nt][0] + s[nt][1];
            rs1 += s[nt][2] + s[nt][3];
        }
        rs0 += __shfl_xor_sync(0xffffffffu, rs0, 1);
        rs0 += __shfl_xor_sync(0xffffffffu, rs0, 2);
        rs1 += __shfl_xor_sync(0xffffffffu, rs1, 1);
        rs1 += __shfl_xor_sync(0xffffffffu, rs1, 2);

        l0 = l0 * alpha0 + rs0;
        l1 = l1 * alpha1 + rs1;
        m0 = mn0; m1 = mn1;
#pragma unroll
        for (int nt = 0; nt < 8; nt++) {
            oacc[nt][0] *= alpha0; oacc[nt][1] *= alpha0;
            oacc[nt][2] *= alpha1; oacc[nt][3] *= alpha1;
        }

        // PV: A-frags = packed S (C-frag layout == fp16 A-frag layout);
        //     B-frags = ldmatrix.trans on V[k][d].
        const uint32_t vBase = sV + p * (64 * AKP * 2);
#pragma unroll
        for (int kk = 0; kk < 4; kk++) {
            uint32_t a0 = packh2(s[2 * kk][0],     s[2 * kk][1]);
            uint32_t a1 = packh2(s[2 * kk][2],     s[2 * kk][3]);
            uint32_t a2 = packh2(s[2 * kk + 1][0], s[2 * kk + 1][1]);
            uint32_t a3 = packh2(s[2 * kk + 1][2], s[2 * kk + 1][3]);
#pragma unroll
            for (int nt2 = 0; nt2 < 4; nt2++) {
                uint32_t ub[4];
                ldsm4t(ub, vBase + (kk * 16 + v_row) * (AKP * 2) + nt2 * 32 + v_byt);
                mma16(oacc[nt2 * 2],     a0, a1, a2, a3, ub[0], ub[1]);
                mma16(oacc[nt2 * 2 + 1], a0, a1, a2, a3, ub[2], ub[3]);
            }
        }
        __syncthreads();
        if (kb + 2 < NB) load_blk(kb + 2, p);
    }

    const float inv0 = 1.0f / l0;
    const float inv1 = 1.0f / l1;
#pragma unroll
    for (int nt = 0; nt < 8; nt++) {
        const int col = nt * 8 + 2 * tig;
        __half* o0 = O + base + (size_t)(q0 + qb + g) * D_MODEL + col;
        __half* o1 = O + base + (size_t)(q0 + qb + g + 8) * D_MODEL + col;
        *(__half2*)o0 = __floats2half2_rn(oacc[nt][0] * inv0, oacc[nt][1] * inv0);
        *(__half2*)o1 = __floats2half2_rn(oacc[nt][2] * inv1, oacc[nt][3] * inv1);
    }
}

// ---------------------------------------------------------------------------
// Launch
// ---------------------------------------------------------------------------
extern "C" void kernel_launch(void* const* d_in, const int* in_sizes, int n_in,
                              void* d_out, int out_size)
{
    const float* q  = (const float*)d_in[0];
    const float* k  = (const float*)d_in[1];
    const float* v  = (const float*)d_in[2];
    const float* Wq = (const float*)d_in[3];
    const float* bq = (const float*)d_in[4];
    const float* Wk = (const float*)d_in[5];
    const float* bk = (const float*)d_in[6];
    const float* Wv = (const float*)d_in[7];
    const float* bv = (const float*)d_in[8];
    const float* Wo = (const float*)d_in[9];
    const float* bo = (const float*)d_in[10];
    float* out = (float*)d_out;

    __half *pqh, *pkh, *pvh, *pQh, *pKh, *pVh, *pOh, *pWh;
    cudaGetSymbolAddress((void**)&pqh, g_qh);
    cudaGetSymbolAddress((void**)&pkh, g_kh);
    cudaGetSymbolAddress((void**)&pvh, g_vh);
    cudaGetSymbolAddress((void**)&pQh, g_Qh);
    cudaGetSymbolAddress((void**)&pKh, g_Kh);
    cudaGetSymbolAddress((void**)&pVh, g_Vh);
    cudaGetSymbolAddress((void**)&pOh, g_Oh);
    cudaGetSymbolAddress((void**)&pWh, g_Wh);

    cudaFuncSetAttribute(gemm_h<1>, cudaFuncAttributeMaxDynamicSharedMemorySize,
                         GEMM_SMEM);
    cudaFuncSetAttribute(gemm_h<0>, cudaFuncAttributeMaxDynamicSharedMemorySize,
                         GEMM_SMEM);
    cudaFuncSetAttribute(attn_h, cudaFuncAttributeMaxDynamicSharedMemorySize,
                         ATTN_SMEM);

    const int WN = D_MODEL * D_MODEL;
    const int XN = MTOT * D_MODEL;
    cvt_f2h<<<XN / 2048, 256>>>(q, pqh);
    cvt_f2h<<<XN / 2048, 256>>>(k, pkh);
    cvt_f2h<<<XN / 2048, 256>>>(v, pvh);
    cvt_f2h<<<WN / 2048, 256>>>(Wq, pWh + 0 * (size_t)WN);
    cvt_f2h<<<WN / 2048, 256>>>(Wk, pWh + 1 * (size_t)WN);
    cvt_f2h<<<WN / 2048, 256>>>(Wv, pWh + 2 * (size_t)WN);
    cvt_f2h<<<WN / 2048, 256>>>(Wo, pWh + 3 * (size_t)WN);

    dim3 gGemm(D_MODEL / 128, MTOT / 128);  // (8, 64)
    gemm_h<1><<<gGemm, 256, GEMM_SMEM>>>(pqh, pWh + 0 * (size_t)WN, bq, pQh);
    gemm_h<1><<<gGemm, 256, GEMM_SMEM>>>(pkh, pWh + 1 * (size_t)WN, bk, pKh);
    gemm_h<1><<<gGemm, 256, GEMM_SMEM>>>(pvh, pWh + 2 * (size_t)WN, bv, pVh);

    dim3 gAttn(SEQ / 128, BATCH * NUM_HEADS);  // (16, 64)
    attn_h<<<gAttn, 256, ATTN_SMEM>>>(pQh, pKh, pVh, pOh);

    gemm_h<0><<<gGemm, 256, GEMM_SMEM>>>(pOh, pWh + 3 * (size_t)WN, bo, out);
}

// round 7
// speedup vs baseline: 2.0927x; 1.0449x over previous
#include <cuda_runtime.h>
#include <cuda_fp16.h>
#include <math.h>
#include <stdint.h>

#define D_MODEL 1024
#define NUM_HEADS 16
#define DK 64
#define BATCH 4
#define SEQ 2048
#define MTOT (BATCH * SEQ)   // 8192

// Scratch (no allocation allowed) — fp16 intermediates
__device__ __half g_qh[MTOT * D_MODEL];
__device__ __half g_kh[MTOT * D_MODEL];
__device__ __half g_vh[MTOT * D_MODEL];
__device__ __half g_Qh[MTOT * D_MODEL];
__device__ __half g_Kh[MTOT * D_MODEL];
__device__ __half g_Vh[MTOT * D_MODEL];
__device__ __half g_Oh[MTOT * D_MODEL];
__device__ __half g_Wh[4 * D_MODEL * D_MODEL];

// ---------------------------------------------------------------------------
// Helpers
// ---------------------------------------------------------------------------
__device__ __forceinline__ uint32_t packh2(float a, float b) {
    __half2 h = __floats2half2_rn(a, b);
    return *reinterpret_cast<uint32_t*>(&h);
}
__device__ __forceinline__ uint32_t ex2h2(uint32_t x) {
    uint32_t r;
    asm("ex2.approx.f16x2 %0, %1;" : "=r"(r) : "r"(x));
    return r;
}

// D += A*B : m16n8k16 fp16 inputs, fp32 accumulate.
__device__ __forceinline__ void mma16(float c[4], uint32_t a0, uint32_t a1,
                                      uint32_t a2, uint32_t a3,
                                      uint32_t b0, uint32_t b1) {
    asm volatile(
        "mma.sync.aligned.m16n8k16.row.col.f32.f16.f16.f32 "
        "{%0,%1,%2,%3}, {%4,%5,%6,%7}, {%8,%9}, {%0,%1,%2,%3};"
        : "+f"(c[0]), "+f"(c[1]), "+f"(c[2]), "+f"(c[3])
        : "r"(a0), "r"(a1), "r"(a2), "r"(a3), "r"(b0), "r"(b1));
}

__device__ __forceinline__ void ldsm4(uint32_t r[4], uint32_t saddr) {
    asm volatile(
        "ldmatrix.sync.aligned.m8n8.x4.shared.b16 {%0,%1,%2,%3}, [%4];"
        : "=r"(r[0]), "=r"(r[1]), "=r"(r[2]), "=r"(r[3]) : "r"(saddr));
}
__device__ __forceinline__ void ldsm4t(uint32_t r[4], uint32_t saddr) {
    asm volatile(
        "ldmatrix.sync.aligned.m8n8.x4.trans.shared.b16 {%0,%1,%2,%3}, [%4];"
        : "=r"(r[0]), "=r"(r[1]), "=r"(r[2]), "=r"(r[3]) : "r"(saddr));
}

__device__ __forceinline__ void cp_async16(void* smem, const void* gmem) {
    uint32_t s = (uint32_t)__cvta_generic_to_shared(smem);
    asm volatile("cp.async.cg.shared.global [%0], [%1], 16;" :: "r"(s), "l"(gmem));
}
__device__ __forceinline__ void cp_commit() {
    asm volatile("cp.async.commit_group;");
}
template <int N>
__device__ __forceinline__ void cp_wait() {
    asm volatile("cp.async.wait_group %0;" :: "n"(N));
}

// ---------------------------------------------------------------------------
// fp32 -> fp16 RN conversion pass (8 elems/thread)
// ---------------------------------------------------------------------------
__global__ __launch_bounds__(256) void cvt_f2h(const float* __restrict__ src,
                                               __half* __restrict__ dst)
{
    int i = (blockIdx.x * 256 + threadIdx.x) * 8;
    float4 v0 = *(const float4*)(src + i);
    float4 v1 = *(const float4*)(src + i + 4);
    __half2 h[4];
    h[0] = __floats2half2_rn(v0.x, v0.y);
    h[1] = __floats2half2_rn(v0.z, v0.w);
    h[2] = __floats2half2_rn(v1.x, v1.y);
    h[3] = __floats2half2_rn(v1.z, v1.w);
    *(uint4*)(dst + i) = *(uint4*)h;
}

// ---------------------------------------------------------------------------
// fp16 GEMM: C[8192,1024] = A @ W^T + bias. (unchanged from round 6)
// ---------------------------------------------------------------------------
#define HP 40
#define HSTG 4
#define HSTAGE (128 * HP)
#define GEMM_SMEM (HSTG * 2 * HSTAGE * 2)  // 81920 B

template <int OUT_HALF>
__global__ __launch_bounds__(256, 2) void gemm_h(
    const __half* __restrict__ A, const __half* __restrict__ W,
    const float* __restrict__ bias, void* __restrict__ Cout)
{
    extern __shared__ __align__(16) __half sgh[];
    __half* As = sgh;
    __half* Ws = sgh + HSTG * HSTAGE;

    const int tid = threadIdx.x;
    const int lane = tid & 31;
    const int g = lane >> 2, tig = lane & 3;
    const int wid = tid >> 5;
    const int wm = wid & 3;
    const int wn = wid >> 2;
    const int row0 = blockIdx.y * 128;
    const int col0 = blockIdx.x * 128;

    const __half* Ag = A + (size_t)row0 * D_MODEL;
    const __half* Wg = W + (size_t)col0 * D_MODEL;

    const uint32_t sA = (uint32_t)__cvta_generic_to_shared(As);
    const uint32_t sW = (uint32_t)__cvta_generic_to_shared(Ws);

    auto load_stage = [&](int ch, int st) {
        const int kof = ch * 32;
#pragma unroll
        for (int j = 0; j < 2; j++) {
            int slot = tid + j * 256;
            int r = slot >> 2, c = (slot & 3) * 8;
            cp_async16(&As[st * HSTAGE + r * HP + c],
                       Ag + (size_t)r * D_MODEL + kof + c);
            cp_async16(&Ws[st * HSTAGE + r * HP + c],
                       Wg + (size_t)r * D_MODEL + kof + c);
        }
        cp_commit();
    };
    load_stage(0, 0);
    load_stage(1, 1);
    load_stage(2, 2);

    float acc[2][8][4];
#pragma unroll
    for (int mt = 0; mt < 2; mt++)
#pragma unroll
        for (int nt = 0; nt < 8; nt++)
#pragma unroll
            for (int i = 0; i < 4; i++) acc[mt][nt][i] = 0.0f;

    const int a_row = lane & 15;
    const int a_byt = (lane >> 4) << 4;
    const int b_row = (lane & 7) + ((lane >> 4) << 3);
    const int b_byt = ((lane >> 3) & 1) << 4;

    const int NCH = D_MODEL / 32;  // 32
    for (int ch = 0; ch < NCH; ch++) {
        const int p = ch & 3;
        if (ch < NCH - 2) cp_wait<2>();
        else if (ch == NCH - 2) cp_wait<1>();
        else cp_wait<0>();
        __syncthreads();
        if (ch + 3 < NCH) load_stage(ch + 3, (ch + 3) & 3);

        const uint32_t aBase = sA + p * (HSTAGE * 2);
        const uint32_t wBase = sW + p * (HSTAGE * 2);
#pragma unroll
        for (int kk = 0; kk < 2; kk++) {
            uint32_t ua[2][4];
#pragma unroll
            for (int mt = 0; mt < 2; mt++)
                ldsm4(ua[mt], aBase + (wm * 32 + mt * 16 + a_row) * (HP * 2)
                              + kk * 32 + a_byt);
#pragma unroll
            for (int nt2 = 0; nt2 < 4; nt2++) {
                uint32_t ub[4];
                ldsm4(ub, wBase + (wn * 64 + nt2 * 16 + b_row) * (HP * 2)
                          + kk * 32 + b_byt);
                mma16(acc[0][nt2 * 2],     ua[0][0], ua[0][1], ua[0][2], ua[0][3], ub[0], ub[1]);
                mma16(acc[1][nt2 * 2],     ua[1][0], ua[1][1], ua[1][2], ua[1][3], ub[0], ub[1]);
                mma16(acc[0][nt2 * 2 + 1], ua[0][0], ua[0][1], ua[0][2], ua[0][3], ub[2], ub[3]);
                mma16(acc[1][nt2 * 2 + 1], ua[1][0], ua[1][1], ua[1][2], ua[1][3], ub[2], ub[3]);
            }
        }
    }

#pragma unroll
    for (int mt = 0; mt < 2; mt++) {
        const int ra = row0 + wm * 32 + mt * 16 + g;
#pragma unroll
        for (int nt = 0; nt < 8; nt++) {
            const int col = col0 + wn * 64 + nt * 8 + 2 * tig;
            const float bz0 = bias[col], bz1 = bias[col + 1];
            float v0 = acc[mt][nt][0] + bz0, v1 = acc[mt][nt][1] + bz1;
            float v2 = acc[mt][nt][2] + bz0, v3 = acc[mt][nt][3] + bz1;
            if (OUT_HALF) {
                __half* C = (__half*)Cout;
                *(__half2*)(C + (size_t)ra * D_MODEL + col) = __floats2half2_rn(v0, v1);
                *(__half2*)(C + (size_t)(ra + 8) * D_MODEL + col) = __floats2half2_rn(v2, v3);
            } else {
                float* C = (float*)Cout;
                *(float2*)(C + (size_t)ra * D_MODEL + col) = make_float2(v0, v1);
                *(float2*)(C + (size_t)(ra + 8) * D_MODEL + col) = make_float2(v2, v3);
            }
        }
    }
}

// ---------------------------------------------------------------------------
// fp16 flash attention v2: base-2 softmax with ex2.approx.f16x2 (half the
// MUFU ops; results ARE the PV A-fragments), 3-stage K/V ring -> single
// __syncthreads per iteration, prefetch overlaps S+softmax+PV.
// Q pre-scaled by 0.125*log2(e) so S comes out of the MMA in base-2 domain.
// smem: K[3][64*AKP] | V[3][64*AKP] = 55296 B; Q staged over K region.
// ---------------------------------------------------------------------------
#define AKP 72
#define NSTG 3
#define ATTN_SMEM (2 * NSTG * 64 * AKP * 2)  // 55296 B

__global__ __launch_bounds__(256, 2) void attn_h(
    const __half* __restrict__ Q, const __half* __restrict__ K,
    const __half* __restrict__ V, __half* __restrict__ O)
{
    extern __shared__ __align__(16) __half smh[];
    __half* Ks = smh;                        // NSTG * 64*AKP
    __half* Vs = smh + NSTG * 64 * AKP;      // NSTG * 64*AKP
    __half* Qst = smh;                       // overlay (128*AKP < NSTG*64*AKP)

    const int tid = threadIdx.x;
    const int lane = tid & 31;
    const int g = lane >> 2, tig = lane & 3;
    const int wid = tid >> 5;
    const int qb = wid * 16;

    const int b = blockIdx.y >> 4;
    const int h = blockIdx.y & 15;
    const int q0 = blockIdx.x * 128;
    const size_t base = (size_t)b * SEQ * D_MODEL + (size_t)h * DK;

    // Stage Q scaled by 0.125*log2(e): S = (q.k)/8 * log2e -> base-2 scores.
    {
        const __half2 sc = __half2half2(__float2half(0.18033688f));
        for (int i = tid; i < 128 * 8; i += 256) {
            int r = i >> 3, c8 = (i & 7) * 8;
            uint4 raw = *(const uint4*)(Q + base + (size_t)(q0 + r) * D_MODEL + c8);
            __half2* hp = (__half2*)&raw;
            hp[0] = __hmul2(hp[0], sc); hp[1] = __hmul2(hp[1], sc);
            hp[2] = __hmul2(hp[2], sc); hp[3] = __hmul2(hp[3], sc);
            *(uint4*)&Qst[r * AKP + c8] = raw;
        }
    }
    __syncthreads();

    const uint32_t sQ = (uint32_t)__cvta_generic_to_shared(Qst);
    const uint32_t sK = (uint32_t)__cvta_generic_to_shared(Ks);
    const uint32_t sV = (uint32_t)__cvta_generic_to_shared(Vs);
    const int a_row = lane & 15;
    const int a_byt = (lane >> 4) << 4;
    const int b_row = (lane & 7) + ((lane >> 4) << 3);
    const int b_byt = ((lane >> 3) & 1) << 4;
    const int v_row = (lane & 7) + (((lane >> 3) & 1) << 3);
    const int v_byt = (lane >> 4) << 4;

    uint32_t qa[4][4];
#pragma unroll
    for (int kk = 0; kk < 4; kk++)
        ldsm4(qa[kk], sQ + (qb + a_row) * (AKP * 2) + kk * 32 + a_byt);
    __syncthreads();

    // K/V block loader: 64 rows x 64 halves (8 x 16B) each
    auto load_blk = [&](int kb, int p) {
#pragma unroll
        for (int j = 0; j < 2; j++) {
            int slot = tid + j * 256;
            int r = slot >> 3, c8 = (slot & 7) * 8;
            const __half* kg = K + base + (size_t)(kb * 64 + r) * D_MODEL + c8;
            const __half* vg = V + base + (size_t)(kb * 64 + r) * D_MODEL + c8;
            cp_async16(&Ks[p * 64 * AKP + r * AKP + c8], kg);
            cp_async16(&Vs[p * 64 * AKP + r * AKP + c8], vg);
        }
        cp_commit();
    };
    load_blk(0, 0);
    load_blk(1, 1);

    float m0 = -INFINITY, m1 = -INFINITY, l0 = 0.0f, l1 = 0.0f;
    float oacc[8][4];
#pragma unroll
    for (int nt = 0; nt < 8; nt++)
#pragma unroll
        for (int i = 0; i < 4; i++) oacc[nt][i] = 0.0f;

    const int NB = SEQ / 64;  // 32
    for (int kb = 0; kb < NB; kb++) {
        const int p = kb % NSTG;
        if (kb < NB - 1) cp_wait<1>(); else cp_wait<0>();
        __syncthreads();
        // Prefetch kb+2 into (kb+2)%3 == (kb-1)%3: released by the sync above.
        if (kb + 2 < NB) load_blk(kb + 2, (kb + 2) % NSTG);

        // S = Q @ K^T  (base-2 domain)
        float s[8][4];
#pragma unroll
        for (int nt = 0; nt < 8; nt++)
#pragma unroll
            for (int i = 0; i < 4; i++) s[nt][i] = 0.0f;

        const uint32_t kBase = sK + p * (64 * AKP * 2);
#pragma unroll
        for (int kk = 0; kk < 4; kk++) {
#pragma unroll
            for (int nt2 = 0; nt2 < 4; nt2++) {
                uint32_t ub[4];
                ldsm4(ub, kBase + (nt2 * 16 + b_row) * (AKP * 2) + kk * 32 + b_byt);
                mma16(s[nt2 * 2],     qa[kk][0], qa[kk][1], qa[kk][2], qa[kk][3], ub[0], ub[1]);
                mma16(s[nt2 * 2 + 1], qa[kk][0], qa[kk][1], qa[kk][2], qa[kk][3], ub[2], ub[3]);
            }
        }

        // Online softmax, base-2: p = 2^(s - mn); alpha = 2^(m - mn)
        float rmax0 = -INFINITY, rmax1 = -INFINITY;
#pragma unroll
        for (int nt = 0; nt < 8; nt++) {
            rmax0 = fmaxf(rmax0, fmaxf(s[nt][0], s[nt][1]));
            rmax1 = fmaxf(rmax1, fmaxf(s[nt][2], s[nt][3]));
        }
        rmax0 = fmaxf(rmax0, __shfl_xor_sync(0xffffffffu, rmax0, 1));
        rmax0 = fmaxf(rmax0, __shfl_xor_sync(0xffffffffu, rmax0, 2));
        rmax1 = fmaxf(rmax1, __shfl_xor_sync(0xffffffffu, rmax1, 1));
        rmax1 = fmaxf(rmax1, __shfl_xor_sync(0xffffffffu, rmax1, 2));

        const float mn0 = fmaxf(m0, rmax0);
        const float mn1 = fmaxf(m1, rmax1);
        const float alpha0 = exp2f(m0 - mn0);
        const float alpha1 = exp2f(m1 - mn1);

        uint32_t ph0[8], ph1[8];
        float rs0 = 0.0f, rs1 = 0.0f;
#pragma unroll
        for (int nt = 0; nt < 8; nt++) {
            ph0[nt] = ex2h2(packh2(s[nt][0] - mn0, s[nt][1] - mn0));
            ph1[nt] = ex2h2(packh2(s[nt][2] - mn1, s[nt][3] - mn1));
            float2 f0 = __half22float2(*(__half2*)&ph0[nt]);
            float2 f1 = __half22float2(*(__half2*)&ph1[nt]);
            rs0 += f0.x + f0.y;
            rs1 += f1.x + f1.y;
        }
        rs0 += __shfl_xor_sync(0xffffffffu, rs0, 1);
        rs0 += __shfl_xor_sync(0xffffffffu, rs0, 2);
        rs1 += __shfl_xor_sync(0xffffffffu, rs1, 1);
        rs1 += __shfl_xor_sync(0xffffffffu, rs1, 2);

        l0 = l0 * alpha0 + rs0;
        l1 = l1 * alpha1 + rs1;
        m0 = mn0; m1 = mn1;
#pragma unroll
        for (int nt = 0; nt < 8; nt++) {
            oacc[nt][0] *= alpha0; oacc[nt][1] *= alpha0;
            oacc[nt][2] *= alpha1; oacc[nt][3] *= alpha1;
        }

        // PV: A-frags = ph (already fp16); B-frags = ldmatrix.trans on V[k][d].
        const uint32_t vBase = sV + p * (64 * AKP * 2);
#pragma unroll
        for (int kk = 0; kk < 4; kk++) {
            uint32_t a0 = ph0[2 * kk];
            uint32_t a1 = ph1[2 * kk];
            uint32_t a2 = ph0[2 * kk + 1];
            uint32_t a3 = ph1[2 * kk + 1];
#pragma unroll
            for (int nt2 = 0; nt2 < 4; nt2++) {
                uint32_t ub[4];
                ldsm4t(ub, vBase + (kk * 16 + v_row) * (AKP * 2) + nt2 * 32 + v_byt);
                mma16(oacc[nt2 * 2],     a0, a1, a2, a3, ub[0], ub[1]);
                mma16(oacc[nt2 * 2 + 1], a0, a1, a2, a3, ub[2], ub[3]);
            }
        }
        // no second sync: 3-stage ring keeps prefetch target disjoint
    }

    const float inv0 = 1.0f / l0;
    const float inv1 = 1.0f / l1;
#pragma unroll
    for (int nt = 0; nt < 8; nt++) {
        const int col = nt * 8 + 2 * tig;
        __half* o0 = O + base + (size_t)(q0 + qb + g) * D_MODEL + col;
        __half* o1 = O + base + (size_t)(q0 + qb + g + 8) * D_MODEL + col;
        *(__half2*)o0 = __floats2half2_rn(oacc[nt][0] * inv0, oacc[nt][1] * inv0);
        *(__half2*)o1 = __floats2half2_rn(oacc[nt][2] * inv1, oacc[nt][3] * inv1);
    }
}

// ---------------------------------------------------------------------------
// Launch
// ---------------------------------------------------------------------------
extern "C" void kernel_launch(void* const* d_in, const int* in_sizes, int n_in,
                              void* d_out, int out_size)
{
    const float* q  = (const float*)d_in[0];
    const float* k  = (const float*)d_in[1];
    const float* v  = (const float*)d_in[2];
    const float* Wq = (const float*)d_in[3];
    const float* bq = (const float*)d_in[4];
    const float* Wk = (const float*)d_in[5];
    const float* bk = (const float*)d_in[6];
    const float* Wv = (const float*)d_in[7];
    const float* bv = (const float*)d_in[8];
    const float* Wo = (const float*)d_in[9];
    const float* bo = (const float*)d_in[10];
    float* out = (float*)d_out;

    __half *pqh, *pkh, *pvh, *pQh, *pKh, *pVh, *pOh, *pWh;
    cudaGetSymbolAddress((void**)&pqh, g_qh);
    cudaGetSymbolAddress((void**)&pkh, g_kh);
    cudaGetSymbolAddress((void**)&pvh, g_vh);
    cudaGetSymbolAddress((void**)&pQh, g_Qh);
    cudaGetSymbolAddress((void**)&pKh, g_Kh);
    cudaGetSymbolAddress((void**)&pVh, g_Vh);
    cudaGetSymbolAddress((void**)&pOh, g_Oh);
    cudaGetSymbolAddress((void**)&pWh, g_Wh);

    cudaFuncSetAttribute(gemm_h<1>, cudaFuncAttributeMaxDynamicSharedMemorySize,
                         GEMM_SMEM);
    cudaFuncSetAttribute(gemm_h<0>, cudaFuncAttributeMaxDynamicSharedMemorySize,
                         GEMM_SMEM);
    cudaFuncSetAttribute(attn_h, cudaFuncAttributeMaxDynamicSharedMemorySize,
                         ATTN_SMEM);

    const int WN = D_MODEL * D_MODEL;
    const int XN = MTOT * D_MODEL;
    cvt_f2h<<<XN / 2048, 256>>>(q, pqh);
    cvt_f2h<<<XN / 2048, 256>>>(k, pkh);
    cvt_f2h<<<XN / 2048, 256>>>(v, pvh);
    cvt_f2h<<<WN / 2048, 256>>>(Wq, pWh + 0 * (size_t)WN);
    cvt_f2h<<<WN / 2048, 256>>>(Wk, pWh + 1 * (size_t)WN);
    cvt_f2h<<<WN / 2048, 256>>>(Wv, pWh + 2 * (size_t)WN);
    cvt_f2h<<<WN / 2048, 256>>>(Wo, pWh + 3 * (size_t)WN);

    dim3 gGemm(D_MODEL / 128, MTOT / 128);  // (8, 64)
    gemm_h<1><<<gGemm, 256, GEMM_SMEM>>>(pqh, pWh + 0 * (size_t)WN, bq, pQh);
    gemm_h<1><<<gGemm, 256, GEMM_SMEM>>>(pkh, pWh + 1 * (size_t)WN, bk, pKh);
    gemm_h<1><<<gGemm, 256, GEMM_SMEM>>>(pvh, pWh + 2 * (size_t)WN, bv, pVh);

    dim3 gAttn(SEQ / 128, BATCH * NUM_HEADS);  // (16, 64)
    attn_h<<<gAttn, 256, ATTN_SMEM>>>(pQh, pKh, pVh, pOh);

    gemm_h<0><<<gGemm, 256, GEMM_SMEM>>>(pOh, pWh + 3 * (size_t)WN, bo, out);
}

// round 8
// speedup vs baseline: 2.3005x; 1.0993x over previous
#include <cuda_runtime.h>
#include <cuda_fp16.h>
#include <math.h>
#include <stdint.h>

#define D_MODEL 1024
#define NUM_HEADS 16
#define DK 64
#define BATCH 4
#define SEQ 2048
#define MTOT (BATCH * SEQ)   // 8192

// Scratch (no allocation allowed) — fp16 intermediates
__device__ __half g_qh[MTOT * D_MODEL];
__device__ __half g_kh[MTOT * D_MODEL];
__device__ __half g_vh[MTOT * D_MODEL];
__device__ __half g_Qh[MTOT * D_MODEL];
__device__ __half g_Kh[MTOT * D_MODEL];
__device__ __half g_Vh[MTOT * D_MODEL];
__device__ __half g_Oh[MTOT * D_MODEL];
__device__ __half g_Wh[4 * D_MODEL * D_MODEL];

// ---------------------------------------------------------------------------
// Helpers
// ---------------------------------------------------------------------------
__device__ __forceinline__ uint32_t packh2(float a, float b) {
    __half2 h = __floats2half2_rn(a, b);
    return *reinterpret_cast<uint32_t*>(&h);
}
__device__ __forceinline__ uint32_t ex2h2(uint32_t x) {
    uint32_t r;
    asm("ex2.approx.f16x2 %0, %1;" : "=r"(r) : "r"(x));
    return r;
}

__device__ __forceinline__ void mma16(float c[4], uint32_t a0, uint32_t a1,
                                      uint32_t a2, uint32_t a3,
                                      uint32_t b0, uint32_t b1) {
    asm volatile(
        "mma.sync.aligned.m16n8k16.row.col.f32.f16.f16.f32 "
        "{%0,%1,%2,%3}, {%4,%5,%6,%7}, {%8,%9}, {%0,%1,%2,%3};"
        : "+f"(c[0]), "+f"(c[1]), "+f"(c[2]), "+f"(c[3])
        : "r"(a0), "r"(a1), "r"(a2), "r"(a3), "r"(b0), "r"(b1));
}

__device__ __forceinline__ void ldsm4(uint32_t r[4], uint32_t saddr) {
    asm volatile(
        "ldmatrix.sync.aligned.m8n8.x4.shared.b16 {%0,%1,%2,%3}, [%4];"
        : "=r"(r[0]), "=r"(r[1]), "=r"(r[2]), "=r"(r[3]) : "r"(saddr));
}
__device__ __forceinline__ void ldsm4t(uint32_t r[4], uint32_t saddr) {
    asm volatile(
        "ldmatrix.sync.aligned.m8n8.x4.trans.shared.b16 {%0,%1,%2,%3}, [%4];"
        : "=r"(r[0]), "=r"(r[1]), "=r"(r[2]), "=r"(r[3]) : "r"(saddr));
}

__device__ __forceinline__ void cp_async16(void* smem, const void* gmem) {
    uint32_t s = (uint32_t)__cvta_generic_to_shared(smem);
    asm volatile("cp.async.cg.shared.global [%0], [%1], 16;" :: "r"(s), "l"(gmem));
}
__device__ __forceinline__ void cp_commit() {
    asm volatile("cp.async.commit_group;");
}
template <int N>
__device__ __forceinline__ void cp_wait() {
    asm volatile("cp.async.wait_group %0;" :: "n"(N));
}

// ---------------------------------------------------------------------------
// Fused fp32->fp16 conversions (blockIdx.y selects array)
// ---------------------------------------------------------------------------
__global__ __launch_bounds__(256) void cvt3_f2h(
    const float* __restrict__ s0, const float* __restrict__ s1,
    const float* __restrict__ s2,
    __half* __restrict__ d0, __half* __restrict__ d1, __half* __restrict__ d2)
{
    const float* src = (blockIdx.y == 0) ? s0 : (blockIdx.y == 1) ? s1 : s2;
    __half* dst = (blockIdx.y == 0) ? d0 : (blockIdx.y == 1) ? d1 : d2;
    int i = (blockIdx.x * 256 + threadIdx.x) * 8;
    float4 v0 = *(const float4*)(src + i);
    float4 v1 = *(const float4*)(src + i + 4);
    __half2 h[4];
    h[0] = __floats2half2_rn(v0.x, v0.y);
    h[1] = __floats2half2_rn(v0.z, v0.w);
    h[2] = __floats2half2_rn(v1.x, v1.y);
    h[3] = __floats2half2_rn(v1.z, v1.w);
    *(uint4*)(dst + i) = *(uint4*)h;
}

__global__ __launch_bounds__(256) void cvt4_f2h(
    const float* __restrict__ s0, const float* __restrict__ s1,
    const float* __restrict__ s2, const float* __restrict__ s3,
    __half* __restrict__ dst)  // 4 contiguous WN blocks
{
    const float* src = (blockIdx.y == 0) ? s0 : (blockIdx.y == 1) ? s1
                       : (blockIdx.y == 2) ? s2 : s3;
    __half* d = dst + (size_t)blockIdx.y * D_MODEL * D_MODEL;
    int i = (blockIdx.x * 256 + threadIdx.x) * 8;
    float4 v0 = *(const float4*)(src + i);
    float4 v1 = *(const float4*)(src + i + 4);
    __half2 h[4];
    h[0] = __floats2half2_rn(v0.x, v0.y);
    h[1] = __floats2half2_rn(v0.z, v0.w);
    h[2] = __floats2half2_rn(v1.x, v1.y);
    h[3] = __floats2half2_rn(v1.z, v1.w);
    *(uint4*)(d + i) = *(uint4*)h;
}

// ---------------------------------------------------------------------------
// fp16 GEMM v3: 128 threads, 4 warps (2x2), warp tile 64x64, BK=32,
// cp.async 4-stage. MMA:LDSM = 4.0.
// ---------------------------------------------------------------------------
#define HP 40
#define HSTG 4
#define HSTAGE (128 * HP)
#define GEMM_SMEM (HSTG * 2 * HSTAGE * 2)  // 81920 B

template <int OUT_HALF>
__global__ __launch_bounds__(128, 2) void gemm_h(
    const __half* __restrict__ A, const __half* __restrict__ W,
    const float* __restrict__ bias, void* __restrict__ Cout)
{
    extern __shared__ __align__(16) __half sgh[];
    __half* As = sgh;
    __half* Ws = sgh + HSTG * HSTAGE;

    const int tid = threadIdx.x;
    const int lane = tid & 31;
    const int g = lane >> 2, tig = lane & 3;
    const int wid = tid >> 5;
    const int wm = wid & 1;      // row half (64 rows)
    const int wn = wid >> 1;     // col half (64 cols)
    const int row0 = blockIdx.y * 128;
    const int col0 = blockIdx.x * 128;

    const __half* Ag = A + (size_t)row0 * D_MODEL;
    const __half* Wg = W + (size_t)col0 * D_MODEL;

    const uint32_t sA = (uint32_t)__cvta_generic_to_shared(As);
    const uint32_t sW = (uint32_t)__cvta_generic_to_shared(Ws);

    // stage: 128 rows x 32 halves per matrix = 512 x 16B chunks each
    auto load_stage = [&](int ch, int st) {
        const int kof = ch * 32;
#pragma unroll
        for (int j = 0; j < 4; j++) {
            int slot = tid + j * 128;
            int r = slot >> 2, c = (slot & 3) * 8;
            cp_async16(&As[st * HSTAGE + r * HP + c],
                       Ag + (size_t)r * D_MODEL + kof + c);
            cp_async16(&Ws[st * HSTAGE + r * HP + c],
                       Wg + (size_t)r * D_MODEL + kof + c);
        }
        cp_commit();
    };
    load_stage(0, 0);
    load_stage(1, 1);
    load_stage(2, 2);

    float acc[4][8][4];
#pragma unroll
    for (int mt = 0; mt < 4; mt++)
#pragma unroll
        for (int nt = 0; nt < 8; nt++)
#pragma unroll
            for (int i = 0; i < 4; i++) acc[mt][nt][i] = 0.0f;

    const int a_row = lane & 15;
    const int a_byt = (lane >> 4) << 4;
    const int b_row = (lane & 7) + ((lane >> 4) << 3);
    const int b_byt = ((lane >> 3) & 1) << 4;

    const int NCH = D_MODEL / 32;  // 32
    for (int ch = 0; ch < NCH; ch++) {
        const int p = ch & 3;
        if (ch < NCH - 2) cp_wait<2>();
        else if (ch == NCH - 2) cp_wait<1>();
        else cp_wait<0>();
        __syncthreads();
        if (ch + 3 < NCH) load_stage(ch + 3, (ch + 3) & 3);

        const uint32_t aBase = sA + p * (HSTAGE * 2);
        const uint32_t wBase = sW + p * (HSTAGE * 2);
#pragma unroll
        for (int kk = 0; kk < 2; kk++) {
            uint32_t ua[4][4];
#pragma unroll
            for (int mt = 0; mt < 4; mt++)
                ldsm4(ua[mt], aBase + (wm * 64 + mt * 16 + a_row) * (HP * 2)
                              + kk * 32 + a_byt);
#pragma unroll
            for (int nt2 = 0; nt2 < 4; nt2++) {
                uint32_t ub[4];
                ldsm4(ub, wBase + (wn * 64 + nt2 * 16 + b_row) * (HP * 2)
                          + kk * 32 + b_byt);
#pragma unroll
                for (int mt = 0; mt < 4; mt++) {
                    mma16(acc[mt][nt2 * 2],     ua[mt][0], ua[mt][1], ua[mt][2], ua[mt][3], ub[0], ub[1]);
                    mma16(acc[mt][nt2 * 2 + 1], ua[mt][0], ua[mt][1], ua[mt][2], ua[mt][3], ub[2], ub[3]);
                }
            }
        }
    }

#pragma unroll
    for (int mt = 0; mt < 4; mt++) {
        const int ra = row0 + wm * 64 + mt * 16 + g;
#pragma unroll
        for (int nt = 0; nt < 8; nt++) {
            const int col = col0 + wn * 64 + nt * 8 + 2 * tig;
            const float bz0 = bias[col], bz1 = bias[col + 1];
            float v0 = acc[mt][nt][0] + bz0, v1 = acc[mt][nt][1] + bz1;
            float v2 = acc[mt][nt][2] + bz0, v3 = acc[mt][nt][3] + bz1;
            if (OUT_HALF) {
                __half* C = (__half*)Cout;
                *(__half2*)(C + (size_t)ra * D_MODEL + col) = __floats2half2_rn(v0, v1);
                *(__half2*)(C + (size_t)(ra + 8) * D_MODEL + col) = __floats2half2_rn(v2, v3);
            } else {
                float* C = (float*)Cout;
                *(float2*)(C + (size_t)ra * D_MODEL + col) = make_float2(v0, v1);
                *(float2*)(C + (size_t)(ra + 8) * D_MODEL + col) = make_float2(v2, v3);
            }
        }
    }
}

// ---------------------------------------------------------------------------
// fp16 flash attention v3: 128 threads, 4 warps x 32 q-rows (2 m16 frags),
// Bc=64, base-2 ex2 softmax, 3-stage K/V ring, single sync/iter.
// K/V fragment LDS amortized over 2x the q-rows vs round 7.
// ---------------------------------------------------------------------------
#define AKP 72
#define NSTG 3
#define ATTN_SMEM (2 * NSTG * 64 * AKP * 2)  // 55296 B

__global__ __launch_bounds__(128, 2) void attn_h(
    const __half* __restrict__ Q, const __half* __restrict__ K,
    const __half* __restrict__ V, __half* __restrict__ O)
{
    extern __shared__ __align__(16) __half smh[];
    __half* Ks = smh;
    __half* Vs = smh + NSTG * 64 * AKP;
    __half* Qst = smh;                       // overlay

    const int tid = threadIdx.x;
    const int lane = tid & 31;
    const int g = lane >> 2, tig = lane & 3;
    const int wid = tid >> 5;
    const int qb = wid * 32;                 // warp covers 32 q-rows

    const int b = blockIdx.y >> 4;
    const int h = blockIdx.y & 15;
    const int q0 = blockIdx.x * 128;
    const size_t base = (size_t)b * SEQ * D_MODEL + (size_t)h * DK;

    // Stage Q scaled by 0.125*log2(e) -> base-2 scores out of the MMA.
    {
        const __half2 sc = __half2half2(__float2half(0.18033688f));
        for (int i = tid; i < 128 * 8; i += 128) {
            int r = i >> 3, c8 = (i & 7) * 8;
            uint4 raw = *(const uint4*)(Q + base + (size_t)(q0 + r) * D_MODEL + c8);
            __half2* hp = (__half2*)&raw;
            hp[0] = __hmul2(hp[0], sc); hp[1] = __hmul2(hp[1], sc);
            hp[2] = __hmul2(hp[2], sc); hp[3] = __hmul2(hp[3], sc);
            *(uint4*)&Qst[r * AKP + c8] = raw;
        }
    }
    __syncthreads();

    const uint32_t sQ = (uint32_t)__cvta_generic_to_shared(Qst);
    const uint32_t sK = (uint32_t)__cvta_generic_to_shared(Ks);
    const uint32_t sV = (uint32_t)__cvta_generic_to_shared(Vs);
    const int a_row = lane & 15;
    const int a_byt = (lane >> 4) << 4;
    const int b_row = (lane & 7) + ((lane >> 4) << 3);
    const int b_byt = ((lane >> 3) & 1) << 4;
    const int v_row = (lane & 7) + (((lane >> 3) & 1) << 3);
    const int v_byt = (lane >> 4) << 4;

    uint32_t qa[2][4][4];
#pragma unroll
    for (int mt = 0; mt < 2; mt++)
#pragma unroll
        for (int kk = 0; kk < 4; kk++)
            ldsm4(qa[mt][kk], sQ + (qb + mt * 16 + a_row) * (AKP * 2) + kk * 32 + a_byt);
    __syncthreads();

    // K/V block loader: 64 rows x 8 16B-chunks each matrix
    auto load_blk = [&](int kb, int p) {
#pragma unroll
        for (int j = 0; j < 4; j++) {
            int slot = tid + j * 128;
            int r = slot >> 3, c8 = (slot & 7) * 8;
            const __half* kg = K + base + (size_t)(kb * 64 + r) * D_MODEL + c8;
            const __half* vg = V + base + (size_t)(kb * 64 + r) * D_MODEL + c8;
            cp_async16(&Ks[p * 64 * AKP + r * AKP + c8], kg);
            cp_async16(&Vs[p * 64 * AKP + r * AKP + c8], vg);
        }
        cp_commit();
    };
    load_blk(0, 0);
    load_blk(1, 1);

    float m[2][2], l[2][2];
    float oacc[2][8][4];
#pragma unroll
    for (int mt = 0; mt < 2; mt++) {
        m[mt][0] = -INFINITY; m[mt][1] = -INFINITY;
        l[mt][0] = 0.0f; l[mt][1] = 0.0f;
#pragma unroll
        for (int nt = 0; nt < 8; nt++)
#pragma unroll
            for (int i = 0; i < 4; i++) oacc[mt][nt][i] = 0.0f;
    }

    const int NB = SEQ / 64;  // 32
    for (int kb = 0; kb < NB; kb++) {
        const int p = kb % NSTG;
        if (kb < NB - 1) cp_wait<1>(); else cp_wait<0>();
        __syncthreads();
        if (kb + 2 < NB) load_blk(kb + 2, (kb + 2) % NSTG);

        // S = Q @ K^T (base-2 domain)
        float s[2][8][4];
#pragma unroll
        for (int mt = 0; mt < 2; mt++)
#pragma unroll
            for (int nt = 0; nt < 8; nt++)
#pragma unroll
                for (int i = 0; i < 4; i++) s[mt][nt][i] = 0.0f;

        const uint32_t kBase = sK + p * (64 * AKP * 2);
#pragma unroll
        for (int kk = 0; kk < 4; kk++) {
#pragma unroll
            for (int nt2 = 0; nt2 < 4; nt2++) {
                uint32_t ub[4];
                ldsm4(ub, kBase + (nt2 * 16 + b_row) * (AKP * 2) + kk * 32 + b_byt);
#pragma unroll
                for (int mt = 0; mt < 2; mt++) {
                    mma16(s[mt][nt2 * 2],     qa[mt][kk][0], qa[mt][kk][1], qa[mt][kk][2], qa[mt][kk][3], ub[0], ub[1]);
                    mma16(s[mt][nt2 * 2 + 1], qa[mt][kk][0], qa[mt][kk][1], qa[mt][kk][2], qa[mt][kk][3], ub[2], ub[3]);
                }
            }
        }

        // Online softmax per m-fragment
        uint32_t ph0[2][8], ph1[2][8];
#pragma unroll
        for (int mt = 0; mt < 2; mt++) {
            float rmax0 = -INFINITY, rmax1 = -INFINITY;
#pragma unroll
            for (int nt = 0; nt < 8; nt++) {
                rmax0 = fmaxf(rmax0, fmaxf(s[mt][nt][0], s[mt][nt][1]));
                rmax1 = fmaxf(rmax1, fmaxf(s[mt][nt][2], s[mt][nt][3]));
            }
            rmax0 = fmaxf(rmax0, __shfl_xor_sync(0xffffffffu, rmax0, 1));
            rmax0 = fmaxf(rmax0, __shfl_xor_sync(0xffffffffu, rmax0, 2));
            rmax1 = fmaxf(rmax1, __shfl_xor_sync(0xffffffffu, rmax1, 1));
            rmax1 = fmaxf(rmax1, __shfl_xor_sync(0xffffffffu, rmax1, 2));

            const float mn0 = fmaxf(m[mt][0], rmax0);
            const float mn1 = fmaxf(m[mt][1], rmax1);
            const float alpha0 = exp2f(m[mt][0] - mn0);
            const float alpha1 = exp2f(m[mt][1] - mn1);

            float rs0 = 0.0f, rs1 = 0.0f;
#pragma unroll
            for (int nt = 0; nt < 8; nt++) {
                ph0[mt][nt] = ex2h2(packh2(s[mt][nt][0] - mn0, s[mt][nt][1] - mn0));
                ph1[mt][nt] = ex2h2(packh2(s[mt][nt][2] - mn1, s[mt][nt][3] - mn1));
                float2 f0 = __half22float2(*(__half2*)&ph0[mt][nt]);
                float2 f1 = __half22float2(*(__half2*)&ph1[mt][nt]);
                rs0 += f0.x + f0.y;
                rs1 += f1.x + f1.y;
            }
            rs0 += __shfl_xor_sync(0xffffffffu, rs0, 1);
            rs0 += __shfl_xor_sync(0xffffffffu, rs0, 2);
            rs1 += __shfl_xor_sync(0xffffffffu, rs1, 1);
            rs1 += __shfl_xor_sync(0xffffffffu, rs1, 2);

            l[mt][0] = l[mt][0] * alpha0 + rs0;
            l[mt][1] = l[mt][1] * alpha1 + rs1;
            m[mt][0] = mn0; m[mt][1] = mn1;
#pragma unroll
            for (int nt = 0; nt < 8; nt++) {
                oacc[mt][nt][0] *= alpha0; oacc[mt][nt][1] *= alpha0;
                oacc[mt][nt][2] *= alpha1; oacc[mt][nt][3] *= alpha1;
            }
        }

        // PV: A-frags = ph (fp16 already); V B-frags ldsm.trans shared over mt.
        const uint32_t vBase = sV + p * (64 * AKP * 2);
#pragma unroll
        for (int kk = 0; kk < 4; kk++) {
#pragma unroll
            for (int nt2 = 0; nt2 < 4; nt2++) {
                uint32_t ub[4];
                ldsm4t(ub, vBase + (kk * 16 + v_row) * (AKP * 2) + nt2 * 32 + v_byt);
#pragma unroll
                for (int mt = 0; mt < 2; mt++) {
                    mma16(oacc[mt][nt2 * 2],     ph0[mt][2 * kk], ph1[mt][2 * kk],
                          ph0[mt][2 * kk + 1], ph1[mt][2 * kk + 1], ub[0], ub[1]);
                    mma16(oacc[mt][nt2 * 2 + 1], ph0[mt][2 * kk], ph1[mt][2 * kk],
                          ph0[mt][2 * kk + 1], ph1[mt][2 * kk + 1], ub[2], ub[3]);
                }
            }
        }
    }

#pragma unroll
    for (int mt = 0; mt < 2; mt++) {
        const float inv0 = 1.0f / l[mt][0];
        const float inv1 = 1.0f / l[mt][1];
#pragma unroll
        for (int nt = 0; nt < 8; nt++) {
            const int col = nt * 8 + 2 * tig;
            __half* o0 = O + base + (size_t)(q0 + qb + mt * 16 + g) * D_MODEL + col;
            __half* o1 = O + base + (size_t)(q0 + qb + mt * 16 + g + 8) * D_MODEL + col;
            *(__half2*)o0 = __floats2half2_rn(oacc[mt][nt][0] * inv0, oacc[mt][nt][1] * inv0);
            *(__half2*)o1 = __floats2half2_rn(oacc[mt][nt][2] * inv1, oacc[mt][nt][3] * inv1);
        }
    }
}

// ---------------------------------------------------------------------------
// Launch
// ---------------------------------------------------------------------------
extern "C" void kernel_launch(void* const* d_in, const int* in_sizes, int n_in,
                              void* d_out, int out_size)
{
    const float* q  = (const float*)d_in[0];
    const float* k  = (const float*)d_in[1];
    const float* v  = (const float*)d_in[2];
    const float* Wq = (const float*)d_in[3];
    const float* bq = (const float*)d_in[4];
    const float* Wk = (const float*)d_in[5];
    const float* bk = (const float*)d_in[6];
    const float* Wv = (const float*)d_in[7];
    const float* bv = (const float*)d_in[8];
    const float* Wo = (const float*)d_in[9];
    const float* bo = (const float*)d_in[10];
    float* out = (float*)d_out;

    __half *pqh, *pkh, *pvh, *pQh, *pKh, *pVh, *pOh, *pWh;
    cudaGetSymbolAddress((void**)&pqh, g_qh);
    cudaGetSymbolAddress((void**)&pkh, g_kh);
    cudaGetSymbolAddress((void**)&pvh, g_vh);
    cudaGetSymbolAddress((void**)&pQh, g_Qh);
    cudaGetSymbolAddress((void**)&pKh, g_Kh);
    cudaGetSymbolAddress((void**)&pVh, g_Vh);
    cudaGetSymbolAddress((void**)&pOh, g_Oh);
    cudaGetSymbolAddress((void**)&pWh, g_Wh);

    cudaFuncSetAttribute(gemm_h<1>, cudaFuncAttributeMaxDynamicSharedMemorySize,
                         GEMM_SMEM);
    cudaFuncSetAttribute(gemm_h<0>, cudaFuncAttributeMaxDynamicSharedMemorySize,
                         GEMM_SMEM);
    cudaFuncSetAttribute(attn_h, cudaFuncAttributeMaxDynamicSharedMemorySize,
                         ATTN_SMEM);

    const int WN = D_MODEL * D_MODEL;
    const int XN = MTOT * D_MODEL;
    dim3 gX(XN / 2048, 3);
    cvt3_f2h<<<gX, 256>>>(q, k, v, pqh, pkh, pvh);
    dim3 gW(WN / 2048, 4);
    cvt4_f2h<<<gW, 256>>>(Wq, Wk, Wv, Wo, pWh);

    dim3 gGemm(D_MODEL / 128, MTOT / 128);  // (8, 64)
    gemm_h<1><<<gGemm, 128, GEMM_SMEM>>>(pqh, pWh + 0 * (size_t)WN, bq, pQh);
    gemm_h<1><<<gGemm, 128, GEMM_SMEM>>>(pkh, pWh + 1 * (size_t)WN, bk, pKh);
    gemm_h<1><<<gGemm, 128, GEMM_SMEM>>>(pvh, pWh + 2 * (size_t)WN, bv, pVh);

    dim3 gAttn(SEQ / 128, BATCH * NUM_HEADS);  // (16, 64)
    attn_h<<<gAttn, 128, ATTN_SMEM>>>(pQh, pKh, pVh, pOh);

    gemm_h<0><<<gGemm, 128, GEMM_SMEM>>>(pOh, pWh + 3 * (size_t)WN, bo, out);
}